// round 15
// baseline (speedup 1.0000x reference)
#include <cuda_runtime.h>
#include <cuda_bf16.h>
#include <cstdint>
#include <math.h>

// ---------------------------------------------------------------------------
// Problem constants
// ---------------------------------------------------------------------------
#define TSEQ  64
#define BATCH 512
#define EBD   256
#define VFD   512
#define SENSD 768
#define H0    512
#define H1    256
#define H2    64
#define C0    1280
#define C1    768
#define C2    320
#define N0    2048         // 4*H0 physical (gate-interleaved, permuted)
#define N1    1024
#define N2    256
#define NROWS (TSEQ * BATCH)

#define E0 (C0 * H0)
#define E1 (C1 * H1)
#define E2 (C2 * H2)
#define EW (E0 + E1 + E2)
#define NBIAS 3328
#define NZ (BATCH * (H0 + H1 + H2))

// ---------------------------------------------------------------------------
// Device-global scratch.
// Weights: per (nb, kc) block = 32 KB: [hi 16KB: 128 n-rows x 64 k bf16,
//   128B rows, SW128][lo 16KB same].
// Hidden states: packed A-tiles, per (mb, kc) block = 16 KB:
//   [hi 8KB: 64 rows x 64 k bf16, SW128][lo 8KB same].
// ---------------------------------------------------------------------------
__device__ float g_W0x[SENSD * N0];   // 16 nb x 12 kc
__device__ float g_W0h[H0 * N0];      // 16 nb x  8 kc
__device__ float g_W1 [C1 * N1];      //  8 nb x 12 kc
__device__ float g_W2 [C2 * N2];      //  2 nb x  5 kc
__device__ float g_b0 [N0];
__device__ float g_b1 [N1];
__device__ float g_b2 [N2];
__device__ float g_U0 [(size_t)NROWS * N0];
__device__ float g_h0 [2 * BATCH * H0];   // packed 2 x (8 mb x 8 kc x 16KB)
__device__ float g_h1 [2 * BATCH * H1];   // packed 2 x (8 mb x 4 kc x 16KB)
__device__ float g_h2 [2 * BATCH * H2];   // packed 2 x (8 mb x 1 kc x 16KB)

// ---------------------------------------------------------------------------
// Helpers (portable PTX only: mma.sync / ldmatrix / cp.async / griddepcontrol)
// ---------------------------------------------------------------------------
__device__ __forceinline__ uint32_t smem_u32(const void* p) {
    uint32_t a;
    asm("{ .reg .u64 t; cvta.to.shared.u64 t, %1; cvt.u32.u64 %0, t; }" : "=r"(a) : "l"(p));
    return a;
}
#define SWZ(o) ((o) ^ (((o) >> 3) & 0x70))

#define LDSM_X4(r0, r1, r2, r3, a) \
    asm volatile("ldmatrix.sync.aligned.m8n8.x4.shared.b16 {%0,%1,%2,%3}, [%4];" \
                 : "=r"(r0), "=r"(r1), "=r"(r2), "=r"(r3) : "r"(a))

__device__ __forceinline__ void mma16816(float (&d)[4], const uint32_t (&a)[4],
                                         const uint32_t (&b)[2]) {
    asm volatile(
        "mma.sync.aligned.m16n8k16.row.col.f32.bf16.bf16.f32 "
        "{%0,%1,%2,%3}, {%4,%5,%6,%7}, {%8,%9}, {%0,%1,%2,%3};"
        : "+f"(d[0]), "+f"(d[1]), "+f"(d[2]), "+f"(d[3])
        : "r"(a[0]), "r"(a[1]), "r"(a[2]), "r"(a[3]), "r"(b[0]), "r"(b[1]));
}

#define CP_ASYNC16(dst, src) \
    asm volatile("cp.async.cg.shared.global [%0], [%1], 16;" :: "r"(dst), "l"(src))
#define CP_COMMIT() asm volatile("cp.async.commit_group;" ::: "memory")
#define CP_WAIT0()  asm volatile("cp.async.wait_group 0;" ::: "memory")

#define GDC_LAUNCH() asm volatile("griddepcontrol.launch_dependents;" ::: "memory")
#define GDC_WAIT()   asm volatile("griddepcontrol.wait;" ::: "memory")

__device__ __forceinline__ uint32_t pack_bf2(__nv_bfloat16 a, __nv_bfloat16 b) {
    uint16_t ua = *(uint16_t*)&a, ub = *(uint16_t*)&b;
    return (uint32_t)ua | ((uint32_t)ub << 16);
}

__host__ __device__ __forceinline__ int perm_col(int n) {
    int grp = n >> 5, L = n & 31, Q = L >> 2, r = L & 3;
    int pl = ((Q & 3) << 1) + (r & 1) + (((Q >> 2) << 1) + (r >> 1)) * 8;
    return (grp << 5) + pl;
}

// ---------------------------------------------------------------------------
// Merged prep kernel: all weights + biases + zero hidden states.
// ---------------------------------------------------------------------------
struct Params {
    const float* w[3][4];
    const float* b[3][4];
    const float* mk[3];
};

__global__ void prep_all(Params pr)
{
    int idx = blockIdx.x * blockDim.x + threadIdx.x;
    if (idx < EW) {
        int l, i, C, H;
        if (idx < E0)            { l = 0; i = idx;           C = C0; H = H0; }
        else if (idx < E0 + E1)  { l = 1; i = idx - E0;      C = C1; H = H1; }
        else                     { l = 2; i = idx - E0 - E1; C = C2; H = H2; }
        int k = i / H, j = i - k * H;
        float mkv = pr.mk[l][(size_t)j * C + k];
        float v[4];
#pragma unroll
        for (int q = 0; q < 4; q++) v[q] = pr.w[l][q][(size_t)j * C + k];
        v[0] *= mkv; v[1] *= mkv;

        char* bas; int KC, kk;
        if (l == 0) {
            if (k < SENSD) { bas = (char*)g_W0x; KC = 12; kk = k; }
            else           { bas = (char*)g_W0h; KC = 8;  kk = k - SENSD; }
        } else if (l == 1) { bas = (char*)g_W1; KC = 12; kk = k; }
        else               { bas = (char*)g_W2; KC = 5;  kk = k; }
        int kc = kk >> 6, kr = kk & 63;
#pragma unroll
        for (int q = 0; q < 4; q++) {
            int P  = perm_col(4 * j + q);
            int nb = P >> 7, nr = P & 127;
            size_t blk = (size_t)(nb * KC + kc) * 32768;
            uint32_t off = SWZ((uint32_t)(nr * 128 + kr * 2));
            float x = v[q];
            __nv_bfloat16 h = __float2bfloat16(x);
            __nv_bfloat16 lo = __float2bfloat16(x - __bfloat162float(h));
            *(__nv_bfloat16*)(bas + blk + off)         = h;
            *(__nv_bfloat16*)(bas + blk + 16384 + off) = lo;
        }
        return;
    }
    if (idx < EW + NBIAS) {
        int c = idx - EW;
        float* bo; const float* b; int j, q;
        if (c < 2048)      { q = c & 3; j = c >> 2; bo = g_b0 + c; b = pr.b[0][q]; }
        else if (c < 3072) { int cc = c - 2048; q = cc & 3; j = cc >> 2; bo = g_b1 + cc; b = pr.b[1][q]; }
        else               { int cc = c - 3072; q = cc & 3; j = cc >> 2; bo = g_b2 + cc; b = pr.b[2][q]; }
        *bo = b[j];
        return;
    }
    int z = idx - EW - NBIAS;
    if (z < NZ) {
        if (z < BATCH * H0)             g_h0[z] = 0.f;
        else if (z < BATCH * (H0 + H1)) g_h1[z - BATCH * H0] = 0.f;
        else                            g_h2[z - BATCH * (H0 + H1)] = 0.f;
    }
}

// ---------------------------------------------------------------------------
// Split-bf16 HMMA GEMM tile (+ optional fused CfC epilogue).
// Tile 64(M) x 128(N), 8 warps (2M x 4N), K-chunks of 64, double-buffered.
//   SENSG=true : A = sensory fp32, converted in-loop; supports kc sub-range
//   SENSG=false: A = packed split-bf16 tiles (hidden states), cp.async'd
// Stage: AH 8K | AL 8K | BH 16K | BL 16K = 48KB, x2 stages.
// Single __syncthreads per chunk: passing sync of iter ch implies all warps
// completed MMA reads of chunk ch-1, making buffer reuse by the post-sync
// prefetch (and pre-sync SENSG stores of chunk ch) race-free.
// pdlw: execute griddepcontrol.wait after the (static) weight prologue.
// ---------------------------------------------------------------------------
#define ST_AH 0
#define ST_AL 8192
#define ST_BH 16384
#define ST_BL 32768
#define ST_BYTES 49152
#define SMEM_BYTES (2 * ST_BYTES)   // 98304

__device__ __forceinline__ void load_a_sens(const float* __restrict__ xa,
                                            const float* __restrict__ xb,
                                            int m0, int k0, int tid, float* ar)
{
#pragma unroll
    for (int it = 0; it < 4; it++) {
        int idx = tid + it * 256;
        int row = idx >> 4, cg = idx & 15;
        int gm  = m0 + row;
        int kg  = k0 + cg * 4;
        int t = gm >> 9, bb = gm & 511;
        const float* src;
        if (kg < EBD) src = xa + (size_t)(bb * TSEQ + t) * EBD + kg;
        else          src = xb + (size_t)(bb * TSEQ + t) * VFD + (kg - EBD);
        float4 v = *(const float4*)src;
        ar[it * 4 + 0] = v.x; ar[it * 4 + 1] = v.y;
        ar[it * 4 + 2] = v.z; ar[it * 4 + 3] = v.w;
    }
}

template<bool SENSG, bool CFC>
__device__ void gemm_tile(const float* __restrict__ xa,   // SENSG: base
                          const float* __restrict__ xb,   // SENSG: visual
                          const char* __restrict__ apA, int KCa,  // packed A pt1
                          const char* __restrict__ apB,           // packed A pt2
                          const char* __restrict__ Wp, int KCtot,
                          int kcBeg, int kcEnd,
                          const float* __restrict__ bias,
                          const float* __restrict__ uadd,
                          char* __restrict__ outPack, int KCout,
                          float* __restrict__ outF, bool accF,
                          int N, int m0, int nbI, char* smem, bool pdlw)
{
    const uint32_t smem_base = smem_u32(smem);

    const int tid  = threadIdx.x;
    const int wid  = tid >> 5;
    const int lane = tid & 31;
    const int wm   = wid >> 2;
    const int wn   = wid & 3;
    const int g    = lane >> 2;
    const int tg   = lane & 3;

    const int n0 = nbI * 128;
    const int mb = m0 >> 6;

    float acc[2][4][4];
#pragma unroll
    for (int a = 0; a < 2; a++)
#pragma unroll
        for (int b = 0; b < 4; b++)
#pragma unroll
            for (int c = 0; c < 4; c++) acc[a][b][c] = 0.f;

    float ar[16];
    if (SENSG) load_a_sens(xa, xb, m0, kcBeg << 6, tid, ar);

    // ---- prologue: weight (static) copy first, then PDL wait, then A ----
    {
        uint32_t dst = smem_base + (uint32_t)(kcBeg & 1) * ST_BYTES;
        const char* ws = Wp + (size_t)(nbI * KCtot + kcBeg) * 32768;
#pragma unroll
        for (int j = 0; j < 8; j++) {
            int i = tid + j * 256;
            CP_ASYNC16(dst + ST_BH + i * 16, ws + i * 16);
        }
        CP_COMMIT();
        if (pdlw) GDC_WAIT();
        if (!SENSG) {
            const char* ab = apA + (size_t)(mb * KCa + kcBeg) * 16384;
#pragma unroll
            for (int j = 0; j < 4; j++) {
                int i = tid + j * 256;
                CP_ASYNC16(dst + ST_AH + i * 16, ab + i * 16);
            }
            CP_COMMIT();
        }
    }

    for (int ch = kcBeg; ch < kcEnd; ch++) {
        const int bsel = ch & 1;
        char* stage = smem + bsel * ST_BYTES;
        const uint32_t stage_u = smem_base + (uint32_t)bsel * ST_BYTES;

        if (SENSG) {
#pragma unroll
            for (int it = 0; it < 4; it++) {
                int idx = tid + it * 256;
                int row = idx >> 4, cg = idx & 15;
                float x0 = ar[it * 4 + 0], x1 = ar[it * 4 + 1];
                float x2 = ar[it * 4 + 2], x3 = ar[it * 4 + 3];
                __nv_bfloat16 h0 = __float2bfloat16(x0);
                __nv_bfloat16 h1 = __float2bfloat16(x1);
                __nv_bfloat16 h2 = __float2bfloat16(x2);
                __nv_bfloat16 h3 = __float2bfloat16(x3);
                __nv_bfloat16 l0 = __float2bfloat16(x0 - __bfloat162float(h0));
                __nv_bfloat16 l1 = __float2bfloat16(x1 - __bfloat162float(h1));
                __nv_bfloat16 l2 = __float2bfloat16(x2 - __bfloat162float(h2));
                __nv_bfloat16 l3 = __float2bfloat16(x3 - __bfloat162float(h3));
                uint32_t off = SWZ((uint32_t)(row * 128 + cg * 8));
                *(uint2*)(stage + ST_AH + off) = make_uint2(pack_bf2(h0, h1), pack_bf2(h2, h3));
                *(uint2*)(stage + ST_AL + off) = make_uint2(pack_bf2(l0, l1), pack_bf2(l2, l3));
            }
        }

        CP_WAIT0();
        __syncthreads();

        // ---- prefetch chunk ch+1 (overlaps MMAs below) ----
        if (ch + 1 < kcEnd) {
            uint32_t dst = smem_base + (uint32_t)((ch + 1) & 1) * ST_BYTES;
            if (!SENSG) {
                int kc = ch + 1;
                const char* ab = (kc < KCa)
                    ? apA + (size_t)(mb * KCa + kc) * 16384
                    : apB + (size_t)(mb * (kcEnd - KCa) + (kc - KCa)) * 16384;
#pragma unroll
                for (int j = 0; j < 4; j++) {
                    int i = tid + j * 256;
                    CP_ASYNC16(dst + ST_AH + i * 16, ab + i * 16);
                }
            }
            const char* ws = Wp + (size_t)(nbI * KCtot + ch + 1) * 32768;
#pragma unroll
            for (int j = 0; j < 8; j++) {
                int i = tid + j * 256;
                CP_ASYNC16(dst + ST_BH + i * 16, ws + i * 16);
            }
            CP_COMMIT();
            if (SENSG) load_a_sens(xa, xb, m0, (ch + 1) << 6, tid, ar);
        }

        // ---- MMAs: 4 k16 steps per 64-chunk ----
        const uint32_t sAh = stage_u + ST_AH;
        const uint32_t sAl = stage_u + ST_AL;
        const uint32_t sBh = stage_u + ST_BH;
        const uint32_t sBl = stage_u + ST_BL;
#pragma unroll
        for (int ks = 0; ks < 4; ks++) {
            uint32_t ah[2][4], al[2][4], bh[4][2], bl[4][2];
#pragma unroll
            for (int mt = 0; mt < 2; mt++) {
                int arow = wm * 32 + mt * 16 + (lane & 15);
                uint32_t aoff = SWZ((uint32_t)(arow * 128 + (ks * 16 + (lane >> 4) * 8) * 2));
                LDSM_X4(ah[mt][0], ah[mt][1], ah[mt][2], ah[mt][3], sAh + aoff);
                LDSM_X4(al[mt][0], al[mt][1], al[mt][2], al[mt][3], sAl + aoff);
            }
#pragma unroll
            for (int nt = 0; nt < 4; nt += 2) {
                int brow = wn * 32 + nt * 8 + ((lane >> 4) & 1) * 8 + (lane & 7);
                uint32_t boff = SWZ((uint32_t)(brow * 128 + (ks * 16 + ((lane >> 3) & 1) * 8) * 2));
                LDSM_X4(bh[nt][0], bh[nt][1], bh[nt + 1][0], bh[nt + 1][1], sBh + boff);
                LDSM_X4(bl[nt][0], bl[nt][1], bl[nt + 1][0], bl[nt + 1][1], sBl + boff);
            }
#pragma unroll
            for (int mt = 0; mt < 2; mt++)
#pragma unroll
                for (int nt = 0; nt < 4; nt++) {
                    mma16816(acc[mt][nt], ah[mt], bh[nt]);
                    mma16816(acc[mt][nt], ah[mt], bl[nt]);
                    mma16816(acc[mt][nt], al[mt], bh[nt]);
                }
        }
        // (no trailing __syncthreads: sync at top of next iter orders reuse)
    }

    // ---- epilogue ----
    if (CFC) {
        const int Hd = N >> 2;
        const int jbase = n0 >> 2;
        char* ob = outPack + (size_t)(mb * KCout + (jbase >> 6)) * 16384;
#pragma unroll
        for (int mt = 0; mt < 2; mt++) {
#pragma unroll
            for (int rh = 0; rh < 2; rh++) {
                int row = m0 + wm * 32 + mt * 16 + rh * 8 + g;
#pragma unroll
                for (int qi = 0; qi < 2; qi++) {
                    float f1  = acc[mt][2 * qi + 0][rh * 2 + 0];
                    float f2  = acc[mt][2 * qi + 0][rh * 2 + 1];
                    float tav = acc[mt][2 * qi + 1][rh * 2 + 0];
                    float tbv = acc[mt][2 * qi + 1][rh * 2 + 1];
                    int j = jbase + wn * 8 + qi * 4 + tg;
                    float4 bq = *(const float4*)(bias + 4 * j);
                    f1 += bq.x; f2 += bq.y; tav += bq.z; tbv += bq.w;
                    if (uadd != nullptr) {
                        int pc = n0 + wn * 32 + qi * 16 + tg * 2;
                        float2 u01 = *(const float2*)(uadd + (size_t)row * N + pc);
                        float2 u23 = *(const float2*)(uadd + (size_t)row * N + pc + 8);
                        f1 += u01.x; f2 += u01.y; tav += u23.x; tbv += u23.y;
                    }
                    float s = 1.f / (1.f + expf(-(tav + tbv)));
                    float h = tanhf(f1) * (1.f - s) + s * tanhf(f2);
                    __nv_bfloat16 hh = __float2bfloat16(h);
                    __nv_bfloat16 hl = __float2bfloat16(h - __bfloat162float(hh));
                    uint32_t off = SWZ((uint32_t)((row & 63) * 128 + (j & 63) * 2));
                    *(__nv_bfloat16*)(ob + off)        = hh;
                    *(__nv_bfloat16*)(ob + 8192 + off) = hl;
                    if (outF != nullptr)
                        outF[(size_t)row * Hd + j] = h;
                }
            }
        }
    } else {
#pragma unroll
        for (int mt = 0; mt < 2; mt++)
#pragma unroll
            for (int rh = 0; rh < 2; rh++) {
                int row = m0 + wm * 32 + mt * 16 + rh * 8 + g;
#pragma unroll
                for (int nt = 0; nt < 4; nt++) {
                    int col = n0 + wn * 32 + nt * 8 + tg * 2;
                    float2 v = make_float2(acc[mt][nt][rh * 2 + 0], acc[mt][nt][rh * 2 + 1]);
                    if (accF) {
                        float2 o = *(float2*)(outF + (size_t)row * N + col);
                        v.x += o.x; v.y += o.y;
                    }
                    *(float2*)(outF + (size_t)row * N + col) = v;
                }
            }
    }
}

// ---------------------------------------------------------------------------
// Head kernel: U0 slices 0..3 (rows 0..2047), grid (16 nb, 32 mb)
// ---------------------------------------------------------------------------
__global__ __launch_bounds__(256, 2)
void u0_head(const float* __restrict__ base, const float* __restrict__ visual)
{
    extern __shared__ char smem[];
    gemm_tile<true, false>(base, visual, nullptr, 0, nullptr,
                           (const char*)g_W0x, 12, 0, 12,
                           nullptr, nullptr, nullptr, 0,
                           g_U0, false,
                           N0, blockIdx.y * 64, blockIdx.x, smem, false);
}

// ---------------------------------------------------------------------------
// Pipelined interval kernel (PDL: dependents launch at top, wait after the
// static-weight prologue). Interval i runs concurrently, no intra-kernel
// cross-CTA sync; kernel boundary (with full-grid PDL wait) = interval sync.
//   CTAs   0..127 : L0(t=i) [8 ch] + (c<104) a 4-chunk U0 weave segment
//   CTAs 128..191 : L1(t=i-1) [12 ch]
//   CTAs 192..207 : L2(t=i-2) [5 ch] + a 4-chunk U0 weave segment
//   CTAs 208..295 : U0 weave slice i+2, tiles 0..87, full 12 ch
// Weave segments (120 total) cover tiles 88..127 of 3 future slices:
//   group0: s=i+4 kc[0,4) write | group1: s=i+3 kc[4,8) accum
//   group2: s=i+2 kc[8,12) accum      (slices 0..3 precomputed by u0_head)
// ---------------------------------------------------------------------------
__global__ __launch_bounds__(256, 2)
void interval_kernel(const float* __restrict__ base, const float* __restrict__ visual,
                     float* __restrict__ dout, int i)
{
    extern __shared__ char smem[];
    const int c = (int)blockIdx.x;

    GDC_LAUNCH();   // let next interval's CTAs start prefetching weights

    // weave segment index for this CTA (-1 = none)
    int segIdx = -1;
    if (c >= 192 && c < 208) segIdx = c - 192;        // 0..15   (L2 CTAs)
    else if (c < 104)        segIdx = 16 + c;         // 16..119 (L0 CTAs)

    if (c < 128) {
        // ---- L0(t=i) ----
        if (i < TSEQ) {
            const char* h0r = (const char*)g_h0 + (size_t)(i & 1) * (BATCH * H0 * 4);
            char*       h0w = (char*)g_h0 + (size_t)((i + 1) & 1) * (BATCH * H0 * 4);
            gemm_tile<false, true>(nullptr, nullptr, h0r, 8, nullptr,
                                   (const char*)g_W0h, 8, 0, 8,
                                   g_b0, g_U0 + (size_t)i * BATCH * N0,
                                   h0w, 8, nullptr, false,
                                   N0, (c >> 4) * 64, c & 15, smem, true);
        } else {
            GDC_WAIT();
        }
    } else if (c < 192) {
        // ---- L1(t=i-1) ----
        int t = i - 1;
        if (t >= 0 && t < TSEQ) {
            const char* h0w = (const char*)g_h0 + (size_t)((t + 1) & 1) * (BATCH * H0 * 4);
            const char* h1r = (const char*)g_h1 + (size_t)(t & 1) * (BATCH * H1 * 4);
            char*       h1w = (char*)g_h1 + (size_t)((t + 1) & 1) * (BATCH * H1 * 4);
            int cc = c - 128;
            gemm_tile<false, true>(nullptr, nullptr, h0w, 8, h1r,
                                   (const char*)g_W1, 12, 0, 12,
                                   g_b1, nullptr,
                                   h1w, 4, nullptr, false,
                                   N1, (cc >> 3) * 64, cc & 7, smem, true);
        } else {
            GDC_WAIT();
        }
        return;
    } else if (c < 208) {
        // ---- L2(t=i-2) ----
        int t = i - 2;
        if (t >= 0 && t < TSEQ) {
            const char* h1w = (const char*)g_h1 + (size_t)((t + 1) & 1) * (BATCH * H1 * 4);
            const char* h2r = (const char*)g_h2 + (size_t)(t & 1) * (BATCH * H2 * 4);
            char*       h2w = (char*)g_h2 + (size_t)((t + 1) & 1) * (BATCH * H2 * 4);
            int cc = c - 192;
            float* o2 = (t == TSEQ - 1) ? dout : nullptr;
            gemm_tile<false, true>(nullptr, nullptr, h1w, 4, h2r,
                                   (const char*)g_W2, 5, 0, 5,
                                   g_b2, nullptr,
                                   h2w, 1, o2, false,
                                   N2, (cc >> 1) * 64, cc & 1, smem, true);
        } else {
            GDC_WAIT();
        }
    } else {
        // ---- weave full tiles 0..87 of slice i+2 ----
        int s = i + 2;
        int tile = c - 208;   // 0..87
        if (s >= 4 && s < TSEQ) {
            gemm_tile<true, false>(base, visual, nullptr, 0, nullptr,
                                   (const char*)g_W0x, 12, 0, 12,
                                   nullptr, nullptr, nullptr, 0,
                                   g_U0, false,
                                   N0, s * BATCH + (tile >> 4) * 64, tile & 15, smem, true);
        } else {
            GDC_WAIT();
        }
        return;
    }

    // ---- weave segment (tiles 88..127, split kc over 3 intervals) ----
    if (segIdx >= 0) {
        int grp  = segIdx / 40;
        int tile = 88 + segIdx % 40;
        int s, kb, ke; bool accum;
        if (grp == 0)      { s = i + 4; kb = 0; ke = 4;  accum = false; }
        else if (grp == 1) { s = i + 3; kb = 4; ke = 8;  accum = true;  }
        else               { s = i + 2; kb = 8; ke = 12; accum = true;  }
        if (s >= 4 && s < TSEQ) {
            __syncthreads();   // protect smem stage reuse across gemm calls
            gemm_tile<true, false>(base, visual, nullptr, 0, nullptr,
                                   (const char*)g_W0x, 12, kb, ke,
                                   nullptr, nullptr, nullptr, 0,
                                   g_U0, accum,
                                   N0, s * BATCH + (tile >> 4) * 64, tile & 15, smem, false);
        }
    }
}

// ---------------------------------------------------------------------------
// kernel_launch — prep_all(1), u0_head(2), intervals 0..65 (3..68) with PDL.
// ncu -s 5 -c 1 profiles interval i=3 (fully representative).
// ---------------------------------------------------------------------------
extern "C" void kernel_launch(void* const* d_in, const int* in_sizes, int n_in,
                              void* d_out, int out_size)
{
    (void)in_sizes; (void)n_in; (void)out_size;
    const float* base   = (const float*)d_in[0];
    const float* visual = (const float*)d_in[1];

    Params pr;
    for (int l = 0; l < 3; l++) {
        int o = 2 + l * 9;
        pr.w[l][0] = (const float*)d_in[o + 0];  pr.b[l][0] = (const float*)d_in[o + 1];
        pr.w[l][1] = (const float*)d_in[o + 2];  pr.b[l][1] = (const float*)d_in[o + 3];
        pr.w[l][2] = (const float*)d_in[o + 4];  pr.b[l][2] = (const float*)d_in[o + 5];
        pr.w[l][3] = (const float*)d_in[o + 6];  pr.b[l][3] = (const float*)d_in[o + 7];
        pr.mk[l]   = (const float*)d_in[o + 8];
    }

    cudaFuncSetAttribute(u0_head,
                         cudaFuncAttributeMaxDynamicSharedMemorySize, SMEM_BYTES);
    cudaFuncSetAttribute(interval_kernel,
                         cudaFuncAttributeMaxDynamicSharedMemorySize, SMEM_BYTES);

    int tot = EW + NBIAS + NZ;
    prep_all<<<(tot + 255) / 256, 256>>>(pr);

    // U0 slices 0..3
    u0_head<<<dim3(16, 32), 256, SMEM_BYTES>>>(base, visual);

    // pipelined intervals with programmatic dependent launch
    for (int i = 0; i < TSEQ + 2; i++) {
        cudaLaunchConfig_t cfg = {};
        cfg.gridDim = dim3(296, 1, 1);
        cfg.blockDim = dim3(256, 1, 1);
        cfg.dynamicSmemBytes = SMEM_BYTES;
        cfg.stream = 0;
        cudaLaunchAttribute at[1];
        at[0].id = cudaLaunchAttributeProgrammaticStreamSerialization;
        at[0].val.programmaticStreamSerializationAllowed = 1;
        cfg.attrs = at;
        cfg.numAttrs = 1;
        cudaLaunchKernelEx(&cfg, interval_kernel, base, visual, (float*)d_out, i);
    }
}

// round 16
// speedup vs baseline: 1.0670x; 1.0670x over previous
#include <cuda_runtime.h>
#include <cuda_bf16.h>
#include <cstdint>
#include <math.h>

// ---------------------------------------------------------------------------
// Problem constants
// ---------------------------------------------------------------------------
#define TSEQ  64
#define BATCH 512
#define EBD   256
#define VFD   512
#define SENSD 768
#define H0    512
#define H1    256
#define H2    64
#define C0    1280
#define C1    768
#define C2    320
#define N0    2048         // 4*H0 physical (gate-interleaved, permuted)
#define N1    1024
#define N2    256
#define NROWS (TSEQ * BATCH)

#define E0 (C0 * H0)
#define E1 (C1 * H1)
#define E2 (C2 * H2)
#define EW (E0 + E1 + E2)
#define NBIAS 3328
#define NZ (BATCH * (H0 + H1 + H2))

// ---------------------------------------------------------------------------
// Device-global scratch.
// Weights: per (nb, kc) block = 32 KB: [hi 16KB: 128 n-rows x 64 k bf16,
//   128B rows, SW128][lo 16KB same].
// Hidden states: packed A-tiles, per (mb, kc) block = 16 KB:
//   [hi 8KB: 64 rows x 64 k bf16, SW128][lo 8KB same].
// ---------------------------------------------------------------------------
__device__ float g_W0x[SENSD * N0];   // 16 nb x 12 kc
__device__ float g_W0h[H0 * N0];      // 16 nb x  8 kc
__device__ float g_W1 [C1 * N1];      //  8 nb x 12 kc
__device__ float g_W2 [C2 * N2];      //  2 nb x  5 kc
__device__ float g_b0 [N0];
__device__ float g_b1 [N1];
__device__ float g_b2 [N2];
__device__ float g_U0 [(size_t)NROWS * N0];
__device__ float g_h0 [2 * BATCH * H0];   // packed 2 x (8 mb x 8 kc x 16KB)
__device__ float g_h1 [2 * BATCH * H1];   // packed 2 x (8 mb x 4 kc x 16KB)
__device__ float g_h2 [2 * BATCH * H2];   // packed 2 x (8 mb x 1 kc x 16KB)

// ---------------------------------------------------------------------------
// Helpers (portable PTX only: mma.sync / ldmatrix / cp.async)
// ---------------------------------------------------------------------------
__device__ __forceinline__ uint32_t smem_u32(const void* p) {
    uint32_t a;
    asm("{ .reg .u64 t; cvta.to.shared.u64 t, %1; cvt.u32.u64 %0, t; }" : "=r"(a) : "l"(p));
    return a;
}
#define SWZ(o) ((o) ^ (((o) >> 3) & 0x70))

#define LDSM_X4(r0, r1, r2, r3, a) \
    asm volatile("ldmatrix.sync.aligned.m8n8.x4.shared.b16 {%0,%1,%2,%3}, [%4];" \
                 : "=r"(r0), "=r"(r1), "=r"(r2), "=r"(r3) : "r"(a))

__device__ __forceinline__ void mma16816(float (&d)[4], const uint32_t (&a)[4],
                                         const uint32_t (&b)[2]) {
    asm volatile(
        "mma.sync.aligned.m16n8k16.row.col.f32.bf16.bf16.f32 "
        "{%0,%1,%2,%3}, {%4,%5,%6,%7}, {%8,%9}, {%0,%1,%2,%3};"
        : "+f"(d[0]), "+f"(d[1]), "+f"(d[2]), "+f"(d[3])
        : "r"(a[0]), "r"(a[1]), "r"(a[2]), "r"(a[3]), "r"(b[0]), "r"(b[1]));
}

#define CP_ASYNC16(dst, src) \
    asm volatile("cp.async.cg.shared.global [%0], [%1], 16;" :: "r"(dst), "l"(src))
#define CP_COMMIT() asm volatile("cp.async.commit_group;" ::: "memory")
#define CP_WAIT0()  asm volatile("cp.async.wait_group 0;" ::: "memory")

__device__ __forceinline__ uint32_t pack_bf2(__nv_bfloat16 a, __nv_bfloat16 b) {
    uint16_t ua = *(uint16_t*)&a, ub = *(uint16_t*)&b;
    return (uint32_t)ua | ((uint32_t)ub << 16);
}

__host__ __device__ __forceinline__ int perm_col(int n) {
    int grp = n >> 5, L = n & 31, Q = L >> 2, r = L & 3;
    int pl = ((Q & 3) << 1) + (r & 1) + (((Q >> 2) << 1) + (r >> 1)) * 8;
    return (grp << 5) + pl;
}

// ---------------------------------------------------------------------------
// Merged prep kernel: all weights + biases + zero hidden states.
// ---------------------------------------------------------------------------
struct Params {
    const float* w[3][4];
    const float* b[3][4];
    const float* mk[3];
};

__global__ void prep_all(Params pr)
{
    int idx = blockIdx.x * blockDim.x + threadIdx.x;
    if (idx < EW) {
        int l, i, C, H;
        if (idx < E0)            { l = 0; i = idx;           C = C0; H = H0; }
        else if (idx < E0 + E1)  { l = 1; i = idx - E0;      C = C1; H = H1; }
        else                     { l = 2; i = idx - E0 - E1; C = C2; H = H2; }
        int k = i / H, j = i - k * H;
        float mkv = pr.mk[l][(size_t)j * C + k];
        float v[4];
#pragma unroll
        for (int q = 0; q < 4; q++) v[q] = pr.w[l][q][(size_t)j * C + k];
        v[0] *= mkv; v[1] *= mkv;

        char* bas; int KC, kk;
        if (l == 0) {
            if (k < SENSD) { bas = (char*)g_W0x; KC = 12; kk = k; }
            else           { bas = (char*)g_W0h; KC = 8;  kk = k - SENSD; }
        } else if (l == 1) { bas = (char*)g_W1; KC = 12; kk = k; }
        else               { bas = (char*)g_W2; KC = 5;  kk = k; }
        int kc = kk >> 6, kr = kk & 63;
#pragma unroll
        for (int q = 0; q < 4; q++) {
            int P  = perm_col(4 * j + q);
            int nb = P >> 7, nr = P & 127;
            size_t blk = (size_t)(nb * KC + kc) * 32768;
            uint32_t off = SWZ((uint32_t)(nr * 128 + kr * 2));
            float x = v[q];
            __nv_bfloat16 h = __float2bfloat16(x);
            __nv_bfloat16 lo = __float2bfloat16(x - __bfloat162float(h));
            *(__nv_bfloat16*)(bas + blk + off)         = h;
            *(__nv_bfloat16*)(bas + blk + 16384 + off) = lo;
        }
        return;
    }
    if (idx < EW + NBIAS) {
        int c = idx - EW;
        float* bo; const float* b; int j, q;
        if (c < 2048)      { q = c & 3; j = c >> 2; bo = g_b0 + c; b = pr.b[0][q]; }
        else if (c < 3072) { int cc = c - 2048; q = cc & 3; j = cc >> 2; bo = g_b1 + cc; b = pr.b[1][q]; }
        else               { int cc = c - 3072; q = cc & 3; j = cc >> 2; bo = g_b2 + cc; b = pr.b[2][q]; }
        *bo = b[j];
        return;
    }
    int z = idx - EW - NBIAS;
    if (z < NZ) {
        if (z < BATCH * H0)             g_h0[z] = 0.f;
        else if (z < BATCH * (H0 + H1)) g_h1[z - BATCH * H0] = 0.f;
        else                            g_h2[z - BATCH * (H0 + H1)] = 0.f;
    }
}

// ---------------------------------------------------------------------------
// Split-bf16 HMMA GEMM tile (+ optional fused CfC epilogue).
// Tile 64(M) x 128(N), 8 warps (2M x 4N), K-chunks of 64, double-buffered.
//   SENSG=true : A = sensory fp32, converted in-loop; supports kc sub-range
//   SENSG=false: A = packed split-bf16 tiles (hidden states), cp.async'd
// Stage: AH 8K | AL 8K | BH 16K | BL 16K = 48KB, x2 stages.
// Single __syncthreads per chunk (at top): passing the sync of iter ch
// implies all warps completed the MMA reads of chunk ch-1, so both the
// pre-sync SENSG stores of chunk ch (buffer ch&1, last read at ch-2) and
// the post-sync prefetch into buffer (ch+1)&1 (last read at ch-1) are
// race-free without a trailing barrier.
// ---------------------------------------------------------------------------
#define ST_AH 0
#define ST_AL 8192
#define ST_BH 16384
#define ST_BL 32768
#define ST_BYTES 49152
#define SMEM_BYTES (2 * ST_BYTES)   // 98304

__device__ __forceinline__ void load_a_sens(const float* __restrict__ xa,
                                            const float* __restrict__ xb,
                                            int m0, int k0, int tid, float* ar)
{
#pragma unroll
    for (int it = 0; it < 4; it++) {
        int idx = tid + it * 256;
        int row = idx >> 4, cg = idx & 15;
        int gm  = m0 + row;
        int kg  = k0 + cg * 4;
        int t = gm >> 9, bb = gm & 511;
        const float* src;
        if (kg < EBD) src = xa + (size_t)(bb * TSEQ + t) * EBD + kg;
        else          src = xb + (size_t)(bb * TSEQ + t) * VFD + (kg - EBD);
        float4 v = *(const float4*)src;
        ar[it * 4 + 0] = v.x; ar[it * 4 + 1] = v.y;
        ar[it * 4 + 2] = v.z; ar[it * 4 + 3] = v.w;
    }
}

template<bool SENSG, bool CFC>
__device__ void gemm_tile(const float* __restrict__ xa,   // SENSG: base
                          const float* __restrict__ xb,   // SENSG: visual
                          const char* __restrict__ apA, int KCa,  // packed A pt1
                          const char* __restrict__ apB,           // packed A pt2
                          const char* __restrict__ Wp, int KCtot,
                          int kcBeg, int kcEnd,
                          const float* __restrict__ bias,
                          const float* __restrict__ uadd,
                          char* __restrict__ outPack, int KCout,
                          float* __restrict__ outF, bool accF,
                          int N, int m0, int nbI, char* smem)
{
    const uint32_t smem_base = smem_u32(smem);

    const int tid  = threadIdx.x;
    const int wid  = tid >> 5;
    const int lane = tid & 31;
    const int wm   = wid >> 2;
    const int wn   = wid & 3;
    const int g    = lane >> 2;
    const int tg   = lane & 3;

    const int n0 = nbI * 128;
    const int mb = m0 >> 6;

    float acc[2][4][4];
#pragma unroll
    for (int a = 0; a < 2; a++)
#pragma unroll
        for (int b = 0; b < 4; b++)
#pragma unroll
            for (int c = 0; c < 4; c++) acc[a][b][c] = 0.f;

    float ar[16];
    if (SENSG) load_a_sens(xa, xb, m0, kcBeg << 6, tid, ar);

    // ---- prologue: async-copy first chunk ----
    {
        uint32_t dst = smem_base + (uint32_t)(kcBeg & 1) * ST_BYTES;
        if (!SENSG) {
            const char* ab = apA + (size_t)(mb * KCa + kcBeg) * 16384;
#pragma unroll
            for (int j = 0; j < 4; j++) {
                int i = tid + j * 256;
                CP_ASYNC16(dst + ST_AH + i * 16, ab + i * 16);
            }
        }
        const char* ws = Wp + (size_t)(nbI * KCtot + kcBeg) * 32768;
#pragma unroll
        for (int j = 0; j < 8; j++) {
            int i = tid + j * 256;
            CP_ASYNC16(dst + ST_BH + i * 16, ws + i * 16);
        }
        CP_COMMIT();
    }

    for (int ch = kcBeg; ch < kcEnd; ch++) {
        const int bsel = ch & 1;
        char* stage = smem + bsel * ST_BYTES;
        const uint32_t stage_u = smem_base + (uint32_t)bsel * ST_BYTES;

        if (SENSG) {
#pragma unroll
            for (int it = 0; it < 4; it++) {
                int idx = tid + it * 256;
                int row = idx >> 4, cg = idx & 15;
                float x0 = ar[it * 4 + 0], x1 = ar[it * 4 + 1];
                float x2 = ar[it * 4 + 2], x3 = ar[it * 4 + 3];
                __nv_bfloat16 h0 = __float2bfloat16(x0);
                __nv_bfloat16 h1 = __float2bfloat16(x1);
                __nv_bfloat16 h2 = __float2bfloat16(x2);
                __nv_bfloat16 h3 = __float2bfloat16(x3);
                __nv_bfloat16 l0 = __float2bfloat16(x0 - __bfloat162float(h0));
                __nv_bfloat16 l1 = __float2bfloat16(x1 - __bfloat162float(h1));
                __nv_bfloat16 l2 = __float2bfloat16(x2 - __bfloat162float(h2));
                __nv_bfloat16 l3 = __float2bfloat16(x3 - __bfloat162float(h3));
                uint32_t off = SWZ((uint32_t)(row * 128 + cg * 8));
                *(uint2*)(stage + ST_AH + off) = make_uint2(pack_bf2(h0, h1), pack_bf2(h2, h3));
                *(uint2*)(stage + ST_AL + off) = make_uint2(pack_bf2(l0, l1), pack_bf2(l2, l3));
            }
        }

        CP_WAIT0();
        __syncthreads();

        // ---- prefetch chunk ch+1 (overlaps MMAs below) ----
        if (ch + 1 < kcEnd) {
            uint32_t dst = smem_base + (uint32_t)((ch + 1) & 1) * ST_BYTES;
            if (!SENSG) {
                int kc = ch + 1;
                const char* ab = (kc < KCa)
                    ? apA + (size_t)(mb * KCa + kc) * 16384
                    : apB + (size_t)(mb * (kcEnd - KCa) + (kc - KCa)) * 16384;
#pragma unroll
                for (int j = 0; j < 4; j++) {
                    int i = tid + j * 256;
                    CP_ASYNC16(dst + ST_AH + i * 16, ab + i * 16);
                }
            }
            const char* ws = Wp + (size_t)(nbI * KCtot + ch + 1) * 32768;
#pragma unroll
            for (int j = 0; j < 8; j++) {
                int i = tid + j * 256;
                CP_ASYNC16(dst + ST_BH + i * 16, ws + i * 16);
            }
            CP_COMMIT();
            if (SENSG) load_a_sens(xa, xb, m0, (ch + 1) << 6, tid, ar);
        }

        // ---- MMAs: 4 k16 steps per 64-chunk ----
        const uint32_t sAh = stage_u + ST_AH;
        const uint32_t sAl = stage_u + ST_AL;
        const uint32_t sBh = stage_u + ST_BH;
        const uint32_t sBl = stage_u + ST_BL;
#pragma unroll
        for (int ks = 0; ks < 4; ks++) {
            uint32_t ah[2][4], al[2][4], bh[4][2], bl[4][2];
#pragma unroll
            for (int mt = 0; mt < 2; mt++) {
                int arow = wm * 32 + mt * 16 + (lane & 15);
                uint32_t aoff = SWZ((uint32_t)(arow * 128 + (ks * 16 + (lane >> 4) * 8) * 2));
                LDSM_X4(ah[mt][0], ah[mt][1], ah[mt][2], ah[mt][3], sAh + aoff);
                LDSM_X4(al[mt][0], al[mt][1], al[mt][2], al[mt][3], sAl + aoff);
            }
#pragma unroll
            for (int nt = 0; nt < 4; nt += 2) {
                int brow = wn * 32 + nt * 8 + ((lane >> 4) & 1) * 8 + (lane & 7);
                uint32_t boff = SWZ((uint32_t)(brow * 128 + (ks * 16 + ((lane >> 3) & 1) * 8) * 2));
                LDSM_X4(bh[nt][0], bh[nt][1], bh[nt + 1][0], bh[nt + 1][1], sBh + boff);
                LDSM_X4(bl[nt][0], bl[nt][1], bl[nt + 1][0], bl[nt + 1][1], sBl + boff);
            }
#pragma unroll
            for (int mt = 0; mt < 2; mt++)
#pragma unroll
                for (int nt = 0; nt < 4; nt++) {
                    mma16816(acc[mt][nt], ah[mt], bh[nt]);
                    mma16816(acc[mt][nt], ah[mt], bl[nt]);
                    mma16816(acc[mt][nt], al[mt], bh[nt]);
                }
        }
        // (no trailing __syncthreads: top-of-loop sync orders buffer reuse)
    }

    // ---- epilogue ----
    if (CFC) {
        const int Hd = N >> 2;
        const int jbase = n0 >> 2;
        char* ob = outPack + (size_t)(mb * KCout + (jbase >> 6)) * 16384;
#pragma unroll
        for (int mt = 0; mt < 2; mt++) {
#pragma unroll
            for (int rh = 0; rh < 2; rh++) {
                int row = m0 + wm * 32 + mt * 16 + rh * 8 + g;
#pragma unroll
                for (int qi = 0; qi < 2; qi++) {
                    float f1  = acc[mt][2 * qi + 0][rh * 2 + 0];
                    float f2  = acc[mt][2 * qi + 0][rh * 2 + 1];
                    float tav = acc[mt][2 * qi + 1][rh * 2 + 0];
                    float tbv = acc[mt][2 * qi + 1][rh * 2 + 1];
                    int j = jbase + wn * 8 + qi * 4 + tg;
                    float4 bq = *(const float4*)(bias + 4 * j);
                    f1 += bq.x; f2 += bq.y; tav += bq.z; tbv += bq.w;
                    if (uadd != nullptr) {
                        int pc = n0 + wn * 32 + qi * 16 + tg * 2;
                        float2 u01 = *(const float2*)(uadd + (size_t)row * N + pc);
                        float2 u23 = *(const float2*)(uadd + (size_t)row * N + pc + 8);
                        f1 += u01.x; f2 += u01.y; tav += u23.x; tbv += u23.y;
                    }
                    float s = 1.f / (1.f + expf(-(tav + tbv)));
                    float h = tanhf(f1) * (1.f - s) + s * tanhf(f2);
                    __nv_bfloat16 hh = __float2bfloat16(h);
                    __nv_bfloat16 hl = __float2bfloat16(h - __bfloat162float(hh));
                    uint32_t off = SWZ((uint32_t)((row & 63) * 128 + (j & 63) * 2));
                    *(__nv_bfloat16*)(ob + off)        = hh;
                    *(__nv_bfloat16*)(ob + 8192 + off) = hl;
                    if (outF != nullptr)
                        outF[(size_t)row * Hd + j] = h;
                }
            }
        }
    } else {
#pragma unroll
        for (int mt = 0; mt < 2; mt++)
#pragma unroll
            for (int rh = 0; rh < 2; rh++) {
                int row = m0 + wm * 32 + mt * 16 + rh * 8 + g;
#pragma unroll
                for (int nt = 0; nt < 4; nt++) {
                    int col = n0 + wn * 32 + nt * 8 + tg * 2;
                    float2 v = make_float2(acc[mt][nt][rh * 2 + 0], acc[mt][nt][rh * 2 + 1]);
                    if (accF) {
                        float2 o = *(float2*)(outF + (size_t)row * N + col);
                        v.x += o.x; v.y += o.y;
                    }
                    *(float2*)(outF + (size_t)row * N + col) = v;
                }
            }
    }
}

// ---------------------------------------------------------------------------
// Head kernel: U0 slices 0..3 (rows 0..2047), grid (16 nb, 32 mb)
// ---------------------------------------------------------------------------
__global__ __launch_bounds__(256, 2)
void u0_head(const float* __restrict__ base, const float* __restrict__ visual)
{
    extern __shared__ char smem[];
    gemm_tile<true, false>(base, visual, nullptr, 0, nullptr,
                           (const char*)g_W0x, 12, 0, 12,
                           nullptr, nullptr, nullptr, 0,
                           g_U0, false,
                           N0, blockIdx.y * 64, blockIdx.x, smem);
}

// ---------------------------------------------------------------------------
// Pipelined interval kernel (NO PDL — plain launches; R15 showed PDL-style
// launch machinery regressed this workload). Interval i runs concurrently,
// kernel boundary = interval sync:
//   CTAs   0..127 : L0(t=i) [8 ch] + (c<104) a 4-chunk U0 weave segment
//   CTAs 128..191 : L1(t=i-1) [12 ch]
//   CTAs 192..207 : L2(t=i-2) [5 ch] + a 4-chunk U0 weave segment
//   CTAs 208..295 : U0 weave slice i+2, tiles 0..87, full 12 ch
// Weave segments (120 total) cover tiles 88..127 of 3 future slices:
//   group0: s=i+4 kc[0,4) write | group1: s=i+3 kc[4,8) accum
//   group2: s=i+2 kc[8,12) accum      (slices 0..3 precomputed by u0_head)
// ---------------------------------------------------------------------------
__global__ __launch_bounds__(256, 2)
void interval_kernel(const float* __restrict__ base, const float* __restrict__ visual,
                     float* __restrict__ dout, int i)
{
    extern __shared__ char smem[];
    const int c = (int)blockIdx.x;

    // weave segment index for this CTA (-1 = none)
    int segIdx = -1;
    if (c >= 192 && c < 208) segIdx = c - 192;        // 0..15   (L2 CTAs)
    else if (c < 104)        segIdx = 16 + c;         // 16..119 (L0 CTAs)

    if (c < 128) {
        // ---- L0(t=i) ----
        if (i < TSEQ) {
            const char* h0r = (const char*)g_h0 + (size_t)(i & 1) * (BATCH * H0 * 4);
            char*       h0w = (char*)g_h0 + (size_t)((i + 1) & 1) * (BATCH * H0 * 4);
            gemm_tile<false, true>(nullptr, nullptr, h0r, 8, nullptr,
                                   (const char*)g_W0h, 8, 0, 8,
                                   g_b0, g_U0 + (size_t)i * BATCH * N0,
                                   h0w, 8, nullptr, false,
                                   N0, (c >> 4) * 64, c & 15, smem);
        }
    } else if (c < 192) {
        // ---- L1(t=i-1) ----
        int t = i - 1;
        if (t >= 0 && t < TSEQ) {
            const char* h0w = (const char*)g_h0 + (size_t)((t + 1) & 1) * (BATCH * H0 * 4);
            const char* h1r = (const char*)g_h1 + (size_t)(t & 1) * (BATCH * H1 * 4);
            char*       h1w = (char*)g_h1 + (size_t)((t + 1) & 1) * (BATCH * H1 * 4);
            int cc = c - 128;
            gemm_tile<false, true>(nullptr, nullptr, h0w, 8, h1r,
                                   (const char*)g_W1, 12, 0, 12,
                                   g_b1, nullptr,
                                   h1w, 4, nullptr, false,
                                   N1, (cc >> 3) * 64, cc & 7, smem);
        }
        return;
    } else if (c < 208) {
        // ---- L2(t=i-2) ----
        int t = i - 2;
        if (t >= 0 && t < TSEQ) {
            const char* h1w = (const char*)g_h1 + (size_t)((t + 1) & 1) * (BATCH * H1 * 4);
            const char* h2r = (const char*)g_h2 + (size_t)(t & 1) * (BATCH * H2 * 4);
            char*       h2w = (char*)g_h2 + (size_t)((t + 1) & 1) * (BATCH * H2 * 4);
            int cc = c - 192;
            float* o2 = (t == TSEQ - 1) ? dout : nullptr;
            gemm_tile<false, true>(nullptr, nullptr, h1w, 4, h2r,
                                   (const char*)g_W2, 5, 0, 5,
                                   g_b2, nullptr,
                                   h2w, 1, o2, false,
                                   N2, (cc >> 1) * 64, cc & 1, smem);
        }
    } else {
        // ---- weave full tiles 0..87 of slice i+2 ----
        int s = i + 2;
        int tile = c - 208;   // 0..87
        if (s >= 4 && s < TSEQ) {
            gemm_tile<true, false>(base, visual, nullptr, 0, nullptr,
                                   (const char*)g_W0x, 12, 0, 12,
                                   nullptr, nullptr, nullptr, 0,
                                   g_U0, false,
                                   N0, s * BATCH + (tile >> 4) * 64, tile & 15, smem);
        }
        return;
    }

    // ---- weave segment (tiles 88..127, split kc over 3 intervals) ----
    if (segIdx >= 0) {
        int grp  = segIdx / 40;
        int tile = 88 + segIdx % 40;
        int s, kb, ke; bool accum;
        if (grp == 0)      { s = i + 4; kb = 0; ke = 4;  accum = false; }
        else if (grp == 1) { s = i + 3; kb = 4; ke = 8;  accum = true;  }
        else               { s = i + 2; kb = 8; ke = 12; accum = true;  }
        if (s >= 4 && s < TSEQ) {
            __syncthreads();   // order smem stage reuse across gemm calls
            gemm_tile<true, false>(base, visual, nullptr, 0, nullptr,
                                   (const char*)g_W0x, 12, kb, ke,
                                   nullptr, nullptr, nullptr, 0,
                                   g_U0, accum,
                                   N0, s * BATCH + (tile >> 4) * 64, tile & 15, smem);
        }
    }
}

// ---------------------------------------------------------------------------
// kernel_launch — prep_all(1), u0_head(2), intervals 0..65 (3..68).
// ncu -s 5 -c 1 profiles interval i=3 (fully representative).
// ---------------------------------------------------------------------------
extern "C" void kernel_launch(void* const* d_in, const int* in_sizes, int n_in,
                              void* d_out, int out_size)
{
    (void)in_sizes; (void)n_in; (void)out_size;
    const float* base   = (const float*)d_in[0];
    const float* visual = (const float*)d_in[1];

    Params pr;
    for (int l = 0; l < 3; l++) {
        int o = 2 + l * 9;
        pr.w[l][0] = (const float*)d_in[o + 0];  pr.b[l][0] = (const float*)d_in[o + 1];
        pr.w[l][1] = (const float*)d_in[o + 2];  pr.b[l][1] = (const float*)d_in[o + 3];
        pr.w[l][2] = (const float*)d_in[o + 4];  pr.b[l][2] = (const float*)d_in[o + 5];
        pr.w[l][3] = (const float*)d_in[o + 6];  pr.b[l][3] = (const float*)d_in[o + 7];
        pr.mk[l]   = (const float*)d_in[o + 8];
    }

    cudaFuncSetAttribute(u0_head,
                         cudaFuncAttributeMaxDynamicSharedMemorySize, SMEM_BYTES);
    cudaFuncSetAttribute(interval_kernel,
                         cudaFuncAttributeMaxDynamicSharedMemorySize, SMEM_BYTES);

    int tot = EW + NBIAS + NZ;
    prep_all<<<(tot + 255) / 256, 256>>>(pr);

    // U0 slices 0..3
    u0_head<<<dim3(16, 32), 256, SMEM_BYTES>>>(base, visual);

    // pipelined intervals: L0(i) || L1(i-1) || L2(i-2) || U0-weave(i+2..i+4)
    for (int i = 0; i < TSEQ + 2; i++)
        interval_kernel<<<296, 256, SMEM_BYTES>>>(base, visual, (float*)d_out, i);
}